// round 11
// baseline (speedup 1.0000x reference)
#include <cuda_runtime.h>
#include <cuda_fp16.h>
#include <stdint.h>

#define B_ 4
#define S_ 2048
#define D_ 1024
#define H_ 16
#define HD_ 64
#define M_ (B_*S_)      // 8192
#define N_QKV 3072
#define QKVN (B_*H_*S_*HD_)   // 8388608

typedef __half fp16;

// ---- Pre-split fp16 planes (device globals; allocation-free) ----
__device__ fp16 g_xhi[M_*D_], g_xlo[M_*D_];          // x        [M,K]  (A)
__device__ fp16 g_waT[N_QKV*D_];                     // W_attn^T [N,K]  (B)
__device__ fp16 g_wpT[D_*D_];                        // W_proj^T [N,K]  (B)
__device__ fp16 g_qhi[QKVN], g_qlo[QKVN];            // q [B,H,S,HD]    (A)
__device__ fp16 g_k1[QKVN];                          // k [B,H,S,HD]    (B)
__device__ fp16 g_vT1[QKVN];                         // v [B,H,HD,S]    (B, transposed)
__device__ fp16 g_yhi[M_*D_], g_ylo[M_*D_];          // attn out [M,K]  (A)

extern __shared__ char smem_raw[];

// ---------------------------------------------------------------------------
__device__ __forceinline__ void split_h(float v, fp16& h, fp16& l) {
    h = __float2half_rn(v);
    l = __float2half_rn(v - __half2float(h));
}
__device__ __forceinline__ uint32_t pk2h(fp16 a, fp16 b) {
    __half2 t(a, b);
    return *reinterpret_cast<uint32_t*>(&t);
}
__device__ __forceinline__ uint32_t pk2hf(float a, float b) {
    __half2 t(__float2half_rn(a), __float2half_rn(b));
    return *reinterpret_cast<uint32_t*>(&t);
}
// f32-accum fp16 MMA
__device__ __forceinline__ void mma16816h(float* c, const uint32_t* a, const uint32_t* b) {
    asm volatile(
        "mma.sync.aligned.m16n8k16.row.col.f32.f16.f16.f32 "
        "{%0,%1,%2,%3}, {%4,%5,%6,%7}, {%8,%9}, {%0,%1,%2,%3};"
        : "+f"(c[0]), "+f"(c[1]), "+f"(c[2]), "+f"(c[3])
        : "r"(a[0]), "r"(a[1]), "r"(a[2]), "r"(a[3]), "r"(b[0]), "r"(b[1]));
}
// f16-accum fp16 MMA (C/D packed half2 pair; reg0={c0,c1}, reg1={c2,c3})
__device__ __forceinline__ void mma16816hh(uint32_t* c, const uint32_t* a, const uint32_t* b) {
    asm volatile(
        "mma.sync.aligned.m16n8k16.row.col.f16.f16.f16.f16 "
        "{%0,%1}, {%2,%3,%4,%5}, {%6,%7}, {%0,%1};"
        : "+r"(c[0]), "+r"(c[1])
        : "r"(a[0]), "r"(a[1]), "r"(a[2]), "r"(a[3]), "r"(b[0]), "r"(b[1]));
}
__device__ __forceinline__ uint32_t smem_u32(const void* p) {
    uint32_t a;
    asm("{ .reg .u64 t; cvta.to.shared.u64 t, %1; cvt.u32.u64 %0, t; }" : "=r"(a) : "l"(p));
    return a;
}
#define CP16(dst, src) \
    asm volatile("cp.async.cg.shared.global [%0], [%1], 16;" :: "r"(dst), "l"(src))
#define CP_COMMIT() asm volatile("cp.async.commit_group;")
#define CP_WAIT1()  asm volatile("cp.async.wait_group 1;")
#define CP_WAIT0()  asm volatile("cp.async.wait_group 0;")

// ===========================================================================
// Conversion kernels
// ===========================================================================
__global__ void conv_split_h(const float* __restrict__ src, fp16* __restrict__ hi,
                             fp16* __restrict__ lo, int n4)
{
    int i = blockIdx.x * 256 + threadIdx.x;
    if (i >= n4) return;
    float4 v = reinterpret_cast<const float4*>(src)[i];
    fp16 h0,h1,h2,h3,l0,l1,l2,l3;
    split_h(v.x,h0,l0); split_h(v.y,h1,l1);
    split_h(v.z,h2,l2); split_h(v.w,h3,l3);
    uint2 hw; hw.x = pk2h(h0,h1); hw.y = pk2h(h2,h3);
    uint2 lw; lw.x = pk2h(l0,l1); lw.y = pk2h(l2,l3);
    *reinterpret_cast<uint2*>(hi + i*4) = hw;
    *reinterpret_cast<uint2*>(lo + i*4) = lw;
}

__global__ __launch_bounds__(256) void conv_wT_h(const float* __restrict__ W,
                                                 fp16* __restrict__ T, int N)
{
    __shared__ fp16 sh[64*66];
    const int n0 = blockIdx.x * 64;
    const int k0 = blockIdx.y * 64;
    const int tid = threadIdx.x;
    #pragma unroll
    for (int i = 0; i < 4; i++) {
        int idx = tid + i * 256;
        int r = idx >> 4;
        int c4 = idx & 15;
        float4 v = *reinterpret_cast<const float4*>(W + (size_t)(k0 + r) * N + n0 + c4*4);
        sh[(c4*4+0)*66 + r] = __float2half_rn(v.x);
        sh[(c4*4+1)*66 + r] = __float2half_rn(v.y);
        sh[(c4*4+2)*66 + r] = __float2half_rn(v.z);
        sh[(c4*4+3)*66 + r] = __float2half_rn(v.w);
    }
    __syncthreads();
    const uint32_t* sh32 = reinterpret_cast<const uint32_t*>(sh);
    #pragma unroll
    for (int i = 0; i < 2; i++) {
        int idx = tid + i * 256;
        int n = idx >> 3;
        int ch = idx & 7;
        int sb = (n*66 + ch*8) >> 1;
        uint4 hv = make_uint4(sh32[sb], sh32[sb+1], sh32[sb+2], sh32[sb+3]);
        size_t o = (size_t)(n0 + n) * D_ + k0 + ch*8;
        *reinterpret_cast<uint4*>(T + o) = hv;
    }
}

// ===========================================================================
// GEMM fp16 2-term: CTA 128x256, 8 warps (2m x 4n), warp tile 64x64.
// hi-term -> f32 accum; lo-term -> f16 accum (combined at epilogue).
// KC=32, 2-stage cp.async.
// ===========================================================================
#define LDK2 40
#define PLANEA (128 * LDK2 * 2)               // 10240 bytes
#define PLANEB (256 * LDK2 * 2)               // 20480 bytes
#define STAGE2 (2*PLANEA + PLANEB)            // 40960
#define SMEM_GEMM (2 * STAGE2)                // 81920
#define OF2_AHI 0
#define OF2_ALO PLANEA
#define OF2_B   (2*PLANEA)

template<int N_TOTAL, bool QKV>
__global__ __launch_bounds__(256)
void gemm_mma(const fp16* __restrict__ Ahi, const fp16* __restrict__ Alo,
              const fp16* __restrict__ BT,
              const float* __restrict__ bias, float* __restrict__ out)
{
    const uint32_t sbase = smem_u32(smem_raw);
    const int tid = threadIdx.x;
    const int wid = tid >> 5;
    const int lane = tid & 31;
    const int grp = lane >> 2;
    const int tig = lane & 3;
    const int wm = (wid >> 2) * 64;           // 0 or 64
    const int wn = (wid & 3) * 64;            // 0,64,128,192
    const int bm = blockIdx.y * 128;
    const int bn = blockIdx.x * 256;

    auto load_stage = [&](int c, int st) {
        uint32_t sb = sbase + st * STAGE2;
        // A planes: 128 rows x 4 chunks
        #pragma unroll
        for (int i = 0; i < 2; i++) {
            int idx = tid + i * 256;          // 0..511
            int row = idx >> 2;               // 0..127
            int ch  = idx & 3;
            uint32_t so = row * (LDK2*2) + ch * 16;
            size_t ga = (size_t)(bm + row) * D_ + c * 32 + ch * 8;
            CP16(sb + OF2_AHI + so, Ahi + ga);
            CP16(sb + OF2_ALO + so, Alo + ga);
        }
        // B plane: 256 rows x 4 chunks
        #pragma unroll
        for (int i = 0; i < 4; i++) {
            int idx = tid + i * 256;          // 0..1023
            int row = idx >> 2;               // 0..255
            int ch  = idx & 3;
            uint32_t so = row * (LDK2*2) + ch * 16;
            size_t gb = (size_t)(bn + row) * D_ + c * 32 + ch * 8;
            CP16(sb + OF2_B + so, BT + gb);
        }
        CP_COMMIT();
    };

    float acc[4][8][4];
    uint32_t a16[4][8][2];
    #pragma unroll
    for (int i = 0; i < 4; i++)
        #pragma unroll
        for (int j = 0; j < 8; j++) {
            #pragma unroll
            for (int q = 0; q < 4; q++) acc[i][j][q] = 0.f;
            a16[i][j][0] = 0u; a16[i][j][1] = 0u;
        }

    load_stage(0, 0);
    load_stage(1, 1);

    for (int c = 0; c < 32; c++) {
        if (c < 31) { CP_WAIT1(); } else { CP_WAIT0(); }
        __syncthreads();

        const int st = c & 1;
        const uint32_t* sA_hi = reinterpret_cast<const uint32_t*>(smem_raw + st*STAGE2 + OF2_AHI);
        const uint32_t* sA_lo = reinterpret_cast<const uint32_t*>(smem_raw + st*STAGE2 + OF2_ALO);
        const uint32_t* sB    = reinterpret_cast<const uint32_t*>(smem_raw + st*STAGE2 + OF2_B);

        #pragma unroll
        for (int ks = 0; ks < 2; ks++) {
            const int k0 = ks * 16;
            uint32_t bh[8][2];
            #pragma unroll
            for (int nt = 0; nt < 8; nt++) {
                int ob = ((wn + nt*8 + grp) * LDK2 + k0 + 2*tig) >> 1;
                bh[nt][0] = sB[ob];
                bh[nt][1] = sB[ob + 4];
            }
            #pragma unroll
            for (int mt = 0; mt < 4; mt++) {
                int oa  = ((wm + mt*16 + grp) * LDK2 + k0 + 2*tig) >> 1;
                int oa8 = oa + (8 * LDK2 >> 1);
                uint32_t ah[4], al[4];
                ah[0] = sA_hi[oa];     ah[1] = sA_hi[oa8];
                ah[2] = sA_hi[oa + 4]; ah[3] = sA_hi[oa8 + 4];
                al[0] = sA_lo[oa];     al[1] = sA_lo[oa8];
                al[2] = sA_lo[oa + 4]; al[3] = sA_lo[oa8 + 4];
                #pragma unroll
                for (int nt = 0; nt < 8; nt++) {
                    mma16816h(acc[mt][nt], ah, bh[nt]);
                    mma16816hh(a16[mt][nt], al, bh[nt]);
                }
            }
        }
        __syncthreads();
        if (c + 2 < 32) load_stage(c + 2, st);
    }

    // ---- Epilogue: combine f32 hi-acc + f16 lo-acc ----
    #pragma unroll
    for (int mt = 0; mt < 4; mt++) {
        #pragma unroll
        for (int half = 0; half < 2; half++) {
            int m = bm + wm + mt * 16 + grp + half * 8;
            #pragma unroll
            for (int nt = 0; nt < 8; nt++) {
                int n = bn + wn + nt * 8 + 2 * tig;
                float2 lo = __half22float2(
                    *reinterpret_cast<const __half2*>(&a16[mt][nt][half]));
                float v0 = acc[mt][nt][half*2 + 0] + lo.x + bias[n];
                float v1 = acc[mt][nt][half*2 + 1] + lo.y + bias[n + 1];
                if (QKV) {
                    int which = n >> 10;
                    int d0 = n & 1023;
                    int h = d0 >> 6, hd = d0 & 63;
                    int b = m >> 11, s = m & 2047;
                    if (which == 2) {
                        size_t o = ((size_t)(b*H_ + h)*HD_ + hd)*S_ + s;
                        g_vT1[o]      = __float2half_rn(v0);
                        g_vT1[o + S_] = __float2half_rn(v1);
                    } else if (which == 1) {
                        size_t o = (((size_t)(b*H_ + h)*S_) + s)*HD_ + hd;
                        *reinterpret_cast<uint32_t*>(g_k1 + o) = pk2hf(v0, v1);
                    } else {
                        size_t o = (((size_t)(b*H_ + h)*S_) + s)*HD_ + hd;
                        fp16 h0,l0,h1,l1;
                        split_h(v0,h0,l0); split_h(v1,h1,l1);
                        *reinterpret_cast<uint32_t*>(g_qhi + o) = pk2h(h0, h1);
                        *reinterpret_cast<uint32_t*>(g_qlo + o) = pk2h(l0, l1);
                    }
                } else {
                    *reinterpret_cast<float2*>(out + (size_t)m * N_TOTAL + n) =
                        make_float2(v0, v1);
                }
            }
        }
    }
}

// ===========================================================================
// Flash attention: CTA = 128 q-rows x 64-key tiles, 4 warps x 32 rows.
// Q fragments loaded once via direct LDG (no smem). K/V double-buffered.
// Heavy q-tiles scheduled first.
// ===========================================================================
#define LDKA 72
#define KPL (64 * LDKA * 2)                   // 9216 bytes per plane
#define STG_A (2 * KPL)                       // 18432 (K, V)
#define SMEM_ATTN (2 * STG_A)                 // 36864
#define OFK 0
#define OFV KPL

__global__ __launch_bounds__(128) void attn_mma()
{
    const int qt = (gridDim.x - 1) - blockIdx.x;   // heavy tiles first
    const int bh_ = blockIdx.y;
    const int b  = bh_ >> 4;
    const int h  = bh_ & 15;
    const size_t head = (size_t)bh_ * S_ * HD_;

    const int tid = threadIdx.x;
    const int wid = tid >> 5;
    const int lane = tid & 31;
    const int grp = lane >> 2;
    const int tig = lane & 3;
    const int wm = wid * 32;                  // warp's 32 rows

    const uint32_t sbase = smem_u32(smem_raw);

    auto load_kv = [&](int kt, int st) {
        uint32_t sb = sbase + st * STG_A;
        #pragma unroll
        for (int i = 0; i < 4; i++) {
            int idx = tid + i * 128;          // 0..511
            int row = idx >> 3, ch = idx & 7;
            uint32_t so = row * (LDKA*2) + ch * 16;
            size_t gk = head + (size_t)(kt*64 + row) * HD_ + ch * 8;
            size_t gv = head + (size_t)row * S_ + kt*64 + ch * 8;   // vT [hd][s]
            CP16(sb + OFK + so, g_k1 + gk);
            CP16(sb + OFV + so, g_vT1 + gv);
        }
        CP_COMMIT();
    };

    // ---- Q fragments: direct gmem loads (once per CTA) ----
    uint32_t qh[2][4][4], ql[2][4][4];
    #pragma unroll
    for (int mt = 0; mt < 2; mt++) {
        int r0 = qt*128 + wm + mt*16 + grp;
        #pragma unroll
        for (int ks = 0; ks < 4; ks++) {
            size_t base0 = head + (size_t)r0 * HD_ + ks*16 + 2*tig;
            size_t base8 = base0 + 8 * HD_;
            qh[mt][ks][0] = *reinterpret_cast<const uint32_t*>(g_qhi + base0);
            qh[mt][ks][1] = *reinterpret_cast<const uint32_t*>(g_qhi + base8);
            qh[mt][ks][2] = *reinterpret_cast<const uint32_t*>(g_qhi + base0 + 8);
            qh[mt][ks][3] = *reinterpret_cast<const uint32_t*>(g_qhi + base8 + 8);
            ql[mt][ks][0] = *reinterpret_cast<const uint32_t*>(g_qlo + base0);
            ql[mt][ks][1] = *reinterpret_cast<const uint32_t*>(g_qlo + base8);
            ql[mt][ks][2] = *reinterpret_cast<const uint32_t*>(g_qlo + base0 + 8);
            ql[mt][ks][3] = *reinterpret_cast<const uint32_t*>(g_qlo + base8 + 8);
        }
    }

    float o[2][8][4];
    #pragma unroll
    for (int mt = 0; mt < 2; mt++)
        #pragma unroll
        for (int nt = 0; nt < 8; nt++)
            #pragma unroll
            for (int q = 0; q < 4; q++) o[mt][nt][q] = 0.f;
    float mrow[2][2] = {{-1e30f,-1e30f},{-1e30f,-1e30f}};
    float lrow[2][2] = {{0.f,0.f},{0.f,0.f}};
    const float scale = 0.125f;

    const int kt_max = 2*qt + 1;
    load_kv(0, 0);

    for (int kt = 0; kt <= kt_max; kt++) {
        const int st = kt & 1;
        if (kt < kt_max) { load_kv(kt + 1, st ^ 1); CP_WAIT1(); }
        else             { CP_WAIT0(); }
        __syncthreads();

        const uint32_t* sK32 = reinterpret_cast<const uint32_t*>(smem_raw + st*STG_A + OFK);
        const uint32_t* sV32 = reinterpret_cast<const uint32_t*>(smem_raw + st*STG_A + OFV);

        // ---- S = Q K^T, both m-tiles, K frags shared across mt ----
        float s[2][8][4];
        #pragma unroll
        for (int mt = 0; mt < 2; mt++)
            #pragma unroll
            for (int nt = 0; nt < 8; nt++)
                #pragma unroll
                for (int q = 0; q < 4; q++) s[mt][nt][q] = 0.f;

        #pragma unroll
        for (int nt = 0; nt < 8; nt++) {
            #pragma unroll
            for (int ks = 0; ks < 4; ks++) {
                int ob = ((nt*8 + grp) * LDKA + ks*16 + 2*tig) >> 1;
                uint32_t bf[2];
                bf[0] = sK32[ob]; bf[1] = sK32[ob + 4];
                #pragma unroll
                for (int mt = 0; mt < 2; mt++) {
                    mma16816h(s[mt][nt], qh[mt][ks], bf);
                    mma16816h(s[mt][nt], ql[mt][ks], bf);
                }
            }
        }

        // ---- scale + causal mask (only tiles that can touch diagonal) ----
        #pragma unroll
        for (int mt = 0; mt < 2; mt++)
            #pragma unroll
            for (int nt = 0; nt < 8; nt++)
                #pragma unroll
                for (int q = 0; q < 4; q++) s[mt][nt][q] *= scale;
        if (kt >= 2*qt) {
            #pragma unroll
            for (int mt = 0; mt < 2; mt++) {
                int r0 = qt*128 + wm + mt*16 + grp;
                int r1 = r0 + 8;
                #pragma unroll
                for (int nt = 0; nt < 8; nt++) {
                    int col = kt*64 + nt*8 + 2*tig;
                    if (col     > r0) s[mt][nt][0] = -1e30f;
                    if (col + 1 > r0) s[mt][nt][1] = -1e30f;
                    if (col     > r1) s[mt][nt][2] = -1e30f;
                    if (col + 1 > r1) s[mt][nt][3] = -1e30f;
                }
            }
        }

        // ---- online softmax per m-tile ----
        #pragma unroll
        for (int mt = 0; mt < 2; mt++) {
            float mx0 = -1e30f, mx1 = -1e30f;
            #pragma unroll
            for (int nt = 0; nt < 8; nt++) {
                mx0 = fmaxf(mx0, fmaxf(s[mt][nt][0], s[mt][nt][1]));
                mx1 = fmaxf(mx1, fmaxf(s[mt][nt][2], s[mt][nt][3]));
            }
            mx0 = fmaxf(mx0, __shfl_xor_sync(0xffffffffu, mx0, 1));
            mx0 = fmaxf(mx0, __shfl_xor_sync(0xffffffffu, mx0, 2));
            mx1 = fmaxf(mx1, __shfl_xor_sync(0xffffffffu, mx1, 1));
            mx1 = fmaxf(mx1, __shfl_xor_sync(0xffffffffu, mx1, 2));
            float mn0 = fmaxf(mrow[mt][0], mx0);
            float mn1 = fmaxf(mrow[mt][1], mx1);
            float a0 = __expf(mrow[mt][0] - mn0);
            float a1 = __expf(mrow[mt][1] - mn1);
            float sum0 = 0.f, sum1 = 0.f;
            #pragma unroll
            for (int nt = 0; nt < 8; nt++) {
                s[mt][nt][0] = __expf(s[mt][nt][0] - mn0);
                s[mt][nt][1] = __expf(s[mt][nt][1] - mn0);
                s[mt][nt][2] = __expf(s[mt][nt][2] - mn1);
                s[mt][nt][3] = __expf(s[mt][nt][3] - mn1);
                sum0 += s[mt][nt][0] + s[mt][nt][1];
                sum1 += s[mt][nt][2] + s[mt][nt][3];
            }
            sum0 += __shfl_xor_sync(0xffffffffu, sum0, 1);
            sum0 += __shfl_xor_sync(0xffffffffu, sum0, 2);
            sum1 += __shfl_xor_sync(0xffffffffu, sum1, 1);
            sum1 += __shfl_xor_sync(0xffffffffu, sum1, 2);
            lrow[mt][0] = lrow[mt][0] * a0 + sum0;
            lrow[mt][1] = lrow[mt][1] * a1 + sum1;
            mrow[mt][0] = mn0; mrow[mt][1] = mn1;
            #pragma unroll
            for (int nt = 0; nt < 8; nt++) {
                o[mt][nt][0] *= a0; o[mt][nt][1] *= a0;
                o[mt][nt][2] *= a1; o[mt][nt][3] *= a1;
            }
        }

        // ---- pack P fragments (hi + residual) for BOTH m-tiles; s dies ----
        uint32_t ph[2][4][4], pl[2][4][4];
        #pragma unroll
        for (int mt = 0; mt < 2; mt++) {
            #pragma unroll
            for (int ks = 0; ks < 4; ks++) {
                const float* c0 = s[mt][2*ks];
                const float* c1 = s[mt][2*ks + 1];
                ph[mt][ks][0] = pk2hf(c0[0], c0[1]);
                ph[mt][ks][1] = pk2hf(c0[2], c0[3]);
                ph[mt][ks][2] = pk2hf(c1[0], c1[1]);
                ph[mt][ks][3] = pk2hf(c1[2], c1[3]);
                float r00 = c0[0] - __half2float(__float2half_rn(c0[0]));
                float r01 = c0[1] - __half2float(__float2half_rn(c0[1]));
                float r02 = c0[2] - __half2float(__float2half_rn(c0[2]));
                float r03 = c0[3] - __half2float(__float2half_rn(c0[3]));
                float r10 = c1[0] - __half2float(__float2half_rn(c1[0]));
                float r11 = c1[1] - __half2float(__float2half_rn(c1[1]));
                float r12 = c1[2] - __half2float(__float2half_rn(c1[2]));
                float r13 = c1[3] - __half2float(__float2half_rn(c1[3]));
                pl[mt][ks][0] = pk2hf(r00, r01);
                pl[mt][ks][1] = pk2hf(r02, r03);
                pl[mt][ks][2] = pk2hf(r10, r11);
                pl[mt][ks][3] = pk2hf(r12, r13);
            }
        }

        // ---- O += P V, V frags shared across mt ----
        #pragma unroll
        for (int nt = 0; nt < 8; nt++) {
            #pragma unroll
            for (int ks = 0; ks < 4; ks++) {
                int ob = (nt*8 + grp) * (LDKA/2) + ks*8 + tig;
                uint32_t vh[2];
                vh[0] = sV32[ob]; vh[1] = sV32[ob + 4];
                #pragma unroll
                for (int mt = 0; mt < 2; mt++) {
                    mma16816h(o[mt][nt], ph[mt][ks], vh);
                    mma16816h(o[mt][nt], pl[mt][ks], vh);
                }
            }
        }
        __syncthreads();
    }

    // ---- finalize: write y hi/lo planes ----
    #pragma unroll
    for (int mt = 0; mt < 2; mt++) {
        float inv0 = 1.0f / lrow[mt][0];
        float inv1 = 1.0f / lrow[mt][1];
        int r0 = qt*128 + wm + mt*16 + grp;
        int r1 = r0 + 8;
        #pragma unroll
        for (int nt = 0; nt < 8; nt++) {
            int col = h * HD_ + nt * 8 + 2 * tig;
            float y00 = o[mt][nt][0] * inv0, y01 = o[mt][nt][1] * inv0;
            float y10 = o[mt][nt][2] * inv1, y11 = o[mt][nt][3] * inv1;
            fp16 h0,l0,h1,l1;
            size_t o0 = ((size_t)b * S_ + r0) * D_ + col;
            size_t o1 = ((size_t)b * S_ + r1) * D_ + col;
            split_h(y00,h0,l0); split_h(y01,h1,l1);
            *reinterpret_cast<uint32_t*>(g_yhi + o0) = pk2h(h0,h1);
            *reinterpret_cast<uint32_t*>(g_ylo + o0) = pk2h(l0,l1);
            split_h(y10,h0,l0); split_h(y11,h1,l1);
            *reinterpret_cast<uint32_t*>(g_yhi + o1) = pk2h(h0,h1);
            *reinterpret_cast<uint32_t*>(g_ylo + o1) = pk2h(l0,l1);
        }
    }
}

// ---------------------------------------------------------------------------
extern "C" void kernel_launch(void* const* d_in, const int* in_sizes, int n_in,
                              void* d_out, int out_size)
{
    const float* x      = nullptr;
    const float* W_attn = nullptr;
    const float* b_attn = nullptr;
    const float* W_proj = nullptr;
    const float* b_proj = nullptr;
    for (int i = 0; i < n_in; i++) {
        switch (in_sizes[i]) {
            case B_*S_*D_:    x      = (const float*)d_in[i]; break;
            case D_*3*D_:     W_attn = (const float*)d_in[i]; break;
            case 3*D_:        b_attn = (const float*)d_in[i]; break;
            case D_*D_:       W_proj = (const float*)d_in[i]; break;
            case D_:          b_proj = (const float*)d_in[i]; break;
            default: break;
        }
    }
    float* out = (float*)d_out;

    void *xhi, *xlo, *waT, *wpT, *yhi, *ylo;
    cudaGetSymbolAddress(&xhi, g_xhi); cudaGetSymbolAddress(&xlo, g_xlo);
    cudaGetSymbolAddress(&waT, g_waT); cudaGetSymbolAddress(&wpT, g_wpT);
    cudaGetSymbolAddress(&yhi, g_yhi); cudaGetSymbolAddress(&ylo, g_ylo);

    cudaFuncSetAttribute(gemm_mma<N_QKV, true>,
                         cudaFuncAttributeMaxDynamicSharedMemorySize, SMEM_GEMM);
    cudaFuncSetAttribute(gemm_mma<D_, false>,
                         cudaFuncAttributeMaxDynamicSharedMemorySize, SMEM_GEMM);
    cudaFuncSetAttribute(attn_mma,
                         cudaFuncAttributeMaxDynamicSharedMemorySize, SMEM_ATTN);

    conv_split_h<<<(M_*D_/4 + 255)/256, 256>>>(x, (fp16*)xhi, (fp16*)xlo, M_*D_/4);
    conv_wT_h<<<dim3(N_QKV/64, D_/64), 256>>>(W_attn, (fp16*)waT, N_QKV);
    conv_wT_h<<<dim3(D_/64, D_/64), 256>>>(W_proj, (fp16*)wpT, D_);

    dim3 g1(N_QKV / 256, M_ / 128);   // 12 x 64
    gemm_mma<N_QKV, true><<<g1, 256, SMEM_GEMM>>>(
        (const fp16*)xhi, (const fp16*)xlo, (const fp16*)waT, b_attn, nullptr);

    dim3 g2(S_ / 128, B_ * H_);       // 16 x 64
    attn_mma<<<g2, 128, SMEM_ATTN>>>();

    dim3 g3(D_ / 256, M_ / 128);      // 4 x 64
    gemm_mma<D_, false><<<g3, 256, SMEM_GEMM>>>(
        (const fp16*)yhi, (const fp16*)ylo, (const fp16*)wpT, b_proj, out);
}

// round 14
// speedup vs baseline: 1.1105x; 1.1105x over previous
#include <cuda_runtime.h>
#include <cuda_fp16.h>
#include <stdint.h>

#define B_ 4
#define S_ 2048
#define D_ 1024
#define H_ 16
#define HD_ 64
#define M_ (B_*S_)      // 8192
#define N_QKV 3072
#define QKVN (B_*H_*S_*HD_)   // 8388608

typedef __half fp16;

// ---- Pre-split fp16 planes (device globals; allocation-free) ----
__device__ fp16 g_xhi[M_*D_], g_xlo[M_*D_];          // x        [M,K]  (A)
__device__ fp16 g_waT[N_QKV*D_];                     // W_attn^T [N,K]  (B)
__device__ fp16 g_wpT[D_*D_];                        // W_proj^T [N,K]  (B)
__device__ fp16 g_qhi[QKVN], g_qlo[QKVN];            // q [B,H,S,HD]    (A)
__device__ fp16 g_k1[QKVN];                          // k [B,H,S,HD]    (B)
__device__ fp16 g_vT1[QKVN];                         // v [B,H,HD,S]    (B, transposed)
__device__ fp16 g_yhi[M_*D_], g_ylo[M_*D_];          // attn out [M,K]  (A)

extern __shared__ char smem_raw[];

// ---------------------------------------------------------------------------
__device__ __forceinline__ void split_h(float v, fp16& h, fp16& l) {
    h = __float2half_rn(v);
    l = __float2half_rn(v - __half2float(h));
}
__device__ __forceinline__ uint32_t pk2h(fp16 a, fp16 b) {
    __half2 t(a, b);
    return *reinterpret_cast<uint32_t*>(&t);
}
__device__ __forceinline__ uint32_t pk2hf(float a, float b) {
    __half2 t(__float2half_rn(a), __float2half_rn(b));
    return *reinterpret_cast<uint32_t*>(&t);
}
__device__ __forceinline__ void mma16816h(float* c, const uint32_t* a, const uint32_t* b) {
    asm volatile(
        "mma.sync.aligned.m16n8k16.row.col.f32.f16.f16.f32 "
        "{%0,%1,%2,%3}, {%4,%5,%6,%7}, {%8,%9}, {%0,%1,%2,%3};"
        : "+f"(c[0]), "+f"(c[1]), "+f"(c[2]), "+f"(c[3])
        : "r"(a[0]), "r"(a[1]), "r"(a[2]), "r"(a[3]), "r"(b[0]), "r"(b[1]));
}
__device__ __forceinline__ uint32_t smem_u32(const void* p) {
    uint32_t a;
    asm("{ .reg .u64 t; cvta.to.shared.u64 t, %1; cvt.u32.u64 %0, t; }" : "=r"(a) : "l"(p));
    return a;
}
#define CP16(dst, src) \
    asm volatile("cp.async.cg.shared.global [%0], [%1], 16;" :: "r"(dst), "l"(src))
#define CP_COMMIT() asm volatile("cp.async.commit_group;")
#define CP_WAIT1()  asm volatile("cp.async.wait_group 1;")
#define CP_WAIT0()  asm volatile("cp.async.wait_group 0;")

// ===========================================================================
// Conversion kernels
// ===========================================================================
__global__ void conv_split_h(const float* __restrict__ src, fp16* __restrict__ hi,
                             fp16* __restrict__ lo, int n4)
{
    int i = blockIdx.x * 256 + threadIdx.x;
    if (i >= n4) return;
    float4 v = reinterpret_cast<const float4*>(src)[i];
    fp16 h0,h1,h2,h3,l0,l1,l2,l3;
    split_h(v.x,h0,l0); split_h(v.y,h1,l1);
    split_h(v.z,h2,l2); split_h(v.w,h3,l3);
    uint2 hw; hw.x = pk2h(h0,h1); hw.y = pk2h(h2,h3);
    uint2 lw; lw.x = pk2h(l0,l1); lw.y = pk2h(l2,l3);
    *reinterpret_cast<uint2*>(hi + i*4) = hw;
    *reinterpret_cast<uint2*>(lo + i*4) = lw;
}

__global__ __launch_bounds__(256) void conv_wT_h(const float* __restrict__ W,
                                                 fp16* __restrict__ T, int N)
{
    __shared__ fp16 sh[64*66];
    const int n0 = blockIdx.x * 64;
    const int k0 = blockIdx.y * 64;
    const int tid = threadIdx.x;
    #pragma unroll
    for (int i = 0; i < 4; i++) {
        int idx = tid + i * 256;
        int r = idx >> 4;
        int c4 = idx & 15;
        float4 v = *reinterpret_cast<const float4*>(W + (size_t)(k0 + r) * N + n0 + c4*4);
        sh[(c4*4+0)*66 + r] = __float2half_rn(v.x);
        sh[(c4*4+1)*66 + r] = __float2half_rn(v.y);
        sh[(c4*4+2)*66 + r] = __float2half_rn(v.z);
        sh[(c4*4+3)*66 + r] = __float2half_rn(v.w);
    }
    __syncthreads();
    const uint32_t* sh32 = reinterpret_cast<const uint32_t*>(sh);
    #pragma unroll
    for (int i = 0; i < 2; i++) {
        int idx = tid + i * 256;
        int n = idx >> 3;
        int ch = idx & 7;
        int sb = (n*66 + ch*8) >> 1;
        uint4 hv = make_uint4(sh32[sb], sh32[sb+1], sh32[sb+2], sh32[sb+3]);
        size_t o = (size_t)(n0 + n) * D_ + k0 + ch*8;
        *reinterpret_cast<uint4*>(T + o) = hv;
    }
}

// ===========================================================================
// GEMM fp16 2-term (R9-proven): tile 128x128, KC=32, 2-stage cp.async,
// 2 CTAs/SM. Planes: Ahi, Alo, B (single).
// ===========================================================================
#define LDK2 40
#define PLANE2 (128 * LDK2 * 2)               // 10240 bytes
#define STAGE2 (3 * PLANE2)                   // 30720
#define SMEM_GEMM (2 * STAGE2)                // 61440
#define OF2_AHI 0
#define OF2_ALO PLANE2
#define OF2_B   (2*PLANE2)

template<int N_TOTAL, bool QKV>
__global__ __launch_bounds__(256, 2)
void gemm_mma(const fp16* __restrict__ Ahi, const fp16* __restrict__ Alo,
              const fp16* __restrict__ BT,
              const float* __restrict__ bias, float* __restrict__ out)
{
    const uint32_t sbase = smem_u32(smem_raw);
    const int tid = threadIdx.x;
    const int wid = tid >> 5;
    const int lane = tid & 31;
    const int grp = lane >> 2;
    const int tig = lane & 3;
    const int wm = (wid >> 2) * 64;
    const int wn = (wid & 3) * 32;
    const int bm = blockIdx.y * 128;
    const int bn = blockIdx.x * 128;

    auto load_stage = [&](int c, int st) {
        uint32_t sb = sbase + st * STAGE2;
        #pragma unroll
        for (int i = 0; i < 2; i++) {
            int idx = tid + i * 256;          // 0..511
            int row = idx >> 2;               // 0..127
            int ch  = idx & 3;
            uint32_t so = row * (LDK2*2) + ch * 16;
            size_t ga = (size_t)(bm + row) * D_ + c * 32 + ch * 8;
            size_t gb = (size_t)(bn + row) * D_ + c * 32 + ch * 8;
            CP16(sb + OF2_AHI + so, Ahi + ga);
            CP16(sb + OF2_ALO + so, Alo + ga);
            CP16(sb + OF2_B   + so, BT  + gb);
        }
        CP_COMMIT();
    };

    float acc[4][4][4];
    #pragma unroll
    for (int i = 0; i < 4; i++)
        #pragma unroll
        for (int j = 0; j < 4; j++)
            #pragma unroll
            for (int q = 0; q < 4; q++) acc[i][j][q] = 0.f;

    load_stage(0, 0);
    load_stage(1, 1);

    for (int c = 0; c < 32; c++) {
        if (c < 31) { CP_WAIT1(); } else { CP_WAIT0(); }
        __syncthreads();

        const int st = c & 1;
        const uint32_t* sA_hi = reinterpret_cast<const uint32_t*>(smem_raw + st*STAGE2 + OF2_AHI);
        const uint32_t* sA_lo = reinterpret_cast<const uint32_t*>(smem_raw + st*STAGE2 + OF2_ALO);
        const uint32_t* sB    = reinterpret_cast<const uint32_t*>(smem_raw + st*STAGE2 + OF2_B);

        #pragma unroll
        for (int ks = 0; ks < 2; ks++) {
            const int k0 = ks * 16;
            uint32_t bh[4][2];
            #pragma unroll
            for (int nt = 0; nt < 4; nt++) {
                int ob = ((wn + nt*8 + grp) * LDK2 + k0 + 2*tig) >> 1;
                bh[nt][0] = sB[ob];
                bh[nt][1] = sB[ob + 4];
            }
            #pragma unroll
            for (int mt = 0; mt < 4; mt++) {
                int oa  = ((wm + mt*16 + grp) * LDK2 + k0 + 2*tig) >> 1;
                int oa8 = oa + (8 * LDK2 >> 1);
                uint32_t ah[4], al[4];
                ah[0] = sA_hi[oa];     ah[1] = sA_hi[oa8];
                ah[2] = sA_hi[oa + 4]; ah[3] = sA_hi[oa8 + 4];
                al[0] = sA_lo[oa];     al[1] = sA_lo[oa8];
                al[2] = sA_lo[oa + 4]; al[3] = sA_lo[oa8 + 4];
                #pragma unroll
                for (int nt = 0; nt < 4; nt++) {
                    mma16816h(acc[mt][nt], ah, bh[nt]);
                    mma16816h(acc[mt][nt], al, bh[nt]);
                }
            }
        }
        __syncthreads();
        if (c + 2 < 32) load_stage(c + 2, st);
    }

    // ---- Epilogue ----
    #pragma unroll
    for (int mt = 0; mt < 4; mt++) {
        #pragma unroll
        for (int half = 0; half < 2; half++) {
            int m = bm + wm + mt * 16 + grp + half * 8;
            #pragma unroll
            for (int nt = 0; nt < 4; nt++) {
                int n = bn + wn + nt * 8 + 2 * tig;
                float v0 = acc[mt][nt][half*2 + 0] + bias[n];
                float v1 = acc[mt][nt][half*2 + 1] + bias[n + 1];
                if (QKV) {
                    int which = n >> 10;
                    int d0 = n & 1023;
                    int h = d0 >> 6, hd = d0 & 63;
                    int b = m >> 11, s = m & 2047;
                    if (which == 2) {
                        size_t o = ((size_t)(b*H_ + h)*HD_ + hd)*S_ + s;
                        g_vT1[o]      = __float2half_rn(v0);
                        g_vT1[o + S_] = __float2half_rn(v1);
                    } else if (which == 1) {
                        size_t o = (((size_t)(b*H_ + h)*S_) + s)*HD_ + hd;
                        *reinterpret_cast<uint32_t*>(g_k1 + o) = pk2hf(v0, v1);
                    } else {
                        size_t o = (((size_t)(b*H_ + h)*S_) + s)*HD_ + hd;
                        fp16 h0,l0,h1,l1;
                        split_h(v0,h0,l0); split_h(v1,h1,l1);
                        *reinterpret_cast<uint32_t*>(g_qhi + o) = pk2h(h0, h1);
                        *reinterpret_cast<uint32_t*>(g_qlo + o) = pk2h(l0, l1);
                    }
                } else {
                    *reinterpret_cast<float2*>(out + (size_t)m * N_TOTAL + n) =
                        make_float2(v0, v1);
                }
            }
        }
    }
}

// ===========================================================================
// Flash attention fp16: Q (hi/lo) x K (single); P (single!) x V (single).
// Double-buffered K/V cp.async. Heavy q-tiles scheduled first.
// ===========================================================================
#define LDKA 72
#define APLH (64 * LDKA * 2)                  // 9216 bytes per plane
#define STAGE_A (2 * APLH)                    // 18432 (K, V)
#define SMEM_ATTN (2 * STAGE_A)               // 36864
#define OFK 0
#define OFV APLH

__global__ __launch_bounds__(128) void attn_mma()
{
    const int qt = (gridDim.x - 1) - blockIdx.x;   // heavy tiles first
    const int bh = blockIdx.y;
    const int b  = bh >> 4;
    const int h  = bh & 15;
    const size_t head = (size_t)bh * S_ * HD_;

    const int tid = threadIdx.x;
    const int wid = tid >> 5;
    const int lane = tid & 31;
    const int grp = lane >> 2;
    const int tig = lane & 3;
    const int wm = wid * 16;

    const uint32_t sbase = smem_u32(smem_raw);

    auto load_kv = [&](int kt, int st) {
        uint32_t sb = sbase + st * STAGE_A;
        #pragma unroll
        for (int i = 0; i < 4; i++) {
            int idx = tid + i * 128;          // 0..511
            int row = idx >> 3, ch = idx & 7;
            uint32_t so = row * (LDKA*2) + ch * 16;
            size_t gk = head + (size_t)(kt*64 + row) * HD_ + ch * 8;
            size_t gv = head + (size_t)row * S_ + kt*64 + ch * 8;   // vT [hd][s]
            CP16(sb + OFK + so, g_k1 + gk);
            CP16(sb + OFV + so, g_vT1 + gv);
        }
        CP_COMMIT();
    };

    // ---- Q (hi into stage1-K slot, lo into stage1-V slot); prefetch kt=0 ----
    {
        uint32_t sb = sbase + STAGE_A;
        #pragma unroll
        for (int i = 0; i < 4; i++) {
            int idx = tid + i * 128;
            int row = idx >> 3, ch = idx & 7;
            uint32_t so = row * (LDKA*2) + ch * 16;
            size_t g = head + (size_t)(qt*64 + row) * HD_ + ch * 8;
            CP16(sb + OFK + so, g_qhi + g);
            CP16(sb + OFV + so, g_qlo + g);
        }
        CP_COMMIT();
    }
    load_kv(0, 0);
    CP_WAIT1();                               // Q arrived
    __syncthreads();

    uint32_t qh[4][4], ql[4][4];
    {
        const uint32_t* sQhi = reinterpret_cast<const uint32_t*>(smem_raw + STAGE_A + OFK);
        const uint32_t* sQlo = reinterpret_cast<const uint32_t*>(smem_raw + STAGE_A + OFV);
        #pragma unroll
        for (int ks = 0; ks < 4; ks++) {
            int oa  = ((wm + grp) * LDKA + ks*16 + 2*tig) >> 1;
            int oa8 = oa + (8 * LDKA >> 1);
            qh[ks][0] = sQhi[oa];     qh[ks][1] = sQhi[oa8];
            qh[ks][2] = sQhi[oa + 4]; qh[ks][3] = sQhi[oa8 + 4];
            ql[ks][0] = sQlo[oa];     ql[ks][1] = sQlo[oa8];
            ql[ks][2] = sQlo[oa + 4]; ql[ks][3] = sQlo[oa8 + 4];
        }
    }
    __syncthreads();                          // Q consumed; stage 1 reusable

    float o[8][4];
    #pragma unroll
    for (int nt = 0; nt < 8; nt++)
        #pragma unroll
        for (int q = 0; q < 4; q++) o[nt][q] = 0.f;
    float mrow[2] = {-1e30f, -1e30f};
    float lrow[2] = {0.f, 0.f};
    const float scale = 0.125f;

    for (int kt = 0; kt <= qt; kt++) {
        const int st = kt & 1;
        if (kt < qt) { load_kv(kt + 1, st ^ 1); CP_WAIT1(); }
        else         { CP_WAIT0(); }
        __syncthreads();

        const uint32_t* sK32 = reinterpret_cast<const uint32_t*>(smem_raw + st*STAGE_A + OFK);
        const uint32_t* sV32 = reinterpret_cast<const uint32_t*>(smem_raw + st*STAGE_A + OFV);

        // ---- S = Q K^T (2-term) ----
        float s[8][4];
        #pragma unroll
        for (int nt = 0; nt < 8; nt++)
            #pragma unroll
            for (int q = 0; q < 4; q++) s[nt][q] = 0.f;
        #pragma unroll
        for (int nt = 0; nt < 8; nt++) {
            #pragma unroll
            for (int ks = 0; ks < 4; ks++) {
                int ob = ((nt*8 + grp) * LDKA + ks*16 + 2*tig) >> 1;
                uint32_t bf[2];
                bf[0] = sK32[ob]; bf[1] = sK32[ob + 4];
                mma16816h(s[nt], qh[ks], bf);
                mma16816h(s[nt], ql[ks], bf);
            }
        }

        // ---- scale + causal mask ----
        #pragma unroll
        for (int nt = 0; nt < 8; nt++)
            #pragma unroll
            for (int q = 0; q < 4; q++) s[nt][q] *= scale;
        if (kt == qt) {
            #pragma unroll
            for (int nt = 0; nt < 8; nt++) {
                int col = nt * 8 + 2 * tig;
                int r0 = wm + grp, r1 = r0 + 8;
                if (col     > r0) s[nt][0] = -1e30f;
                if (col + 1 > r0) s[nt][1] = -1e30f;
                if (col     > r1) s[nt][2] = -1e30f;
                if (col + 1 > r1) s[nt][3] = -1e30f;
            }
        }

        // ---- online softmax ----
        float mx0 = -1e30f, mx1 = -1e30f;
        #pragma unroll
        for (int nt = 0; nt < 8; nt++) {
            mx0 = fmaxf(mx0, fmaxf(s[nt][0], s[nt][1]));
            mx1 = fmaxf(mx1, fmaxf(s[nt][2], s[nt][3]));
        }
        mx0 = fmaxf(mx0, __shfl_xor_sync(0xffffffffu, mx0, 1));
        mx0 = fmaxf(mx0, __shfl_xor_sync(0xffffffffu, mx0, 2));
        mx1 = fmaxf(mx1, __shfl_xor_sync(0xffffffffu, mx1, 1));
        mx1 = fmaxf(mx1, __shfl_xor_sync(0xffffffffu, mx1, 2));
        float mn0 = fmaxf(mrow[0], mx0);
        float mn1 = fmaxf(mrow[1], mx1);
        float a0 = __expf(mrow[0] - mn0);
        float a1 = __expf(mrow[1] - mn1);
        float sum0 = 0.f, sum1 = 0.f;
        #pragma unroll
        for (int nt = 0; nt < 8; nt++) {
            s[nt][0] = __expf(s[nt][0] - mn0);
            s[nt][1] = __expf(s[nt][1] - mn0);
            s[nt][2] = __expf(s[nt][2] - mn1);
            s[nt][3] = __expf(s[nt][3] - mn1);
            sum0 += s[nt][0] + s[nt][1];
            sum1 += s[nt][2] + s[nt][3];
        }
        sum0 += __shfl_xor_sync(0xffffffffu, sum0, 1);
        sum0 += __shfl_xor_sync(0xffffffffu, sum0, 2);
        sum1 += __shfl_xor_sync(0xffffffffu, sum1, 1);
        sum1 += __shfl_xor_sync(0xffffffffu, sum1, 2);
        lrow[0] = lrow[0] * a0 + sum0;
        lrow[1] = lrow[1] * a1 + sum1;
        mrow[0] = mn0; mrow[1] = mn1;
        #pragma unroll
        for (int nt = 0; nt < 8; nt++) {
            o[nt][0] *= a0; o[nt][1] *= a0;
            o[nt][2] *= a1; o[nt][3] *= a1;
        }

        // ---- pack P (single fp16 term; weights in [0,1], err ~2^-11) ----
        uint32_t ph[4][4];
        #pragma unroll
        for (int ks = 0; ks < 4; ks++) {
            const float* c0 = s[2*ks];
            const float* c1 = s[2*ks + 1];
            ph[ks][0] = pk2hf(c0[0], c0[1]);
            ph[ks][1] = pk2hf(c0[2], c0[3]);
            ph[ks][2] = pk2hf(c1[0], c1[1]);
            ph[ks][3] = pk2hf(c1[2], c1[3]);
        }

        // ---- O += P V (1-term) ----
        #pragma unroll
        for (int nt = 0; nt < 8; nt++) {
            #pragma unroll
            for (int ks = 0; ks < 4; ks++) {
                int ob = (nt*8 + grp) * (LDKA/2) + ks*8 + tig;
                uint32_t vh[2];
                vh[0] = sV32[ob]; vh[1] = sV32[ob + 4];
                mma16816h(o[nt], ph[ks], vh);
            }
        }
        __syncthreads();
    }

    // ---- finalize: write y hi/lo planes ----
    float inv0 = 1.0f / lrow[0];
    float inv1 = 1.0f / lrow[1];
    int r0 = qt * 64 + wm + grp;
    int r1 = r0 + 8;
    #pragma unroll
    for (int nt = 0; nt < 8; nt++) {
        int col = h * HD_ + nt * 8 + 2 * tig;
        float y00 = o[nt][0] * inv0, y01 = o[nt][1] * inv0;
        float y10 = o[nt][2] * inv1, y11 = o[nt][3] * inv1;
        fp16 h0,l0,h1,l1;
        size_t o0 = ((size_t)b * S_ + r0) * D_ + col;
        size_t o1 = ((size_t)b * S_ + r1) * D_ + col;
        split_h(y00,h0,l0); split_h(y01,h1,l1);
        *reinterpret_cast<uint32_t*>(g_yhi + o0) = pk2h(h0,h1);
        *reinterpret_cast<uint32_t*>(g_ylo + o0) = pk2h(l0,l1);
        split_h(y10,h0,l0); split_h(y11,h1,l1);
        *reinterpret_cast<uint32_t*>(g_yhi + o1) = pk2h(h0,h1);
        *reinterpret_cast<uint32_t*>(g_ylo + o1) = pk2h(l0,l1);
    }
}

// ---------------------------------------------------------------------------
extern "C" void kernel_launch(void* const* d_in, const int* in_sizes, int n_in,
                              void* d_out, int out_size)
{
    const float* x      = nullptr;
    const float* W_attn = nullptr;
    const float* b_attn = nullptr;
    const float* W_proj = nullptr;
    const float* b_proj = nullptr;
    for (int i = 0; i < n_in; i++) {
        switch (in_sizes[i]) {
            case B_*S_*D_:    x      = (const float*)d_in[i]; break;
            case D_*3*D_:     W_attn = (const float*)d_in[i]; break;
            case 3*D_:        b_attn = (const float*)d_in[i]; break;
            case D_*D_:       W_proj = (const float*)d_in[i]; break;
            case D_:          b_proj = (const float*)d_in[i]; break;
            default: break;
        }
    }
    float* out = (float*)d_out;

    void *xhi, *xlo, *waT, *wpT, *yhi, *ylo;
    cudaGetSymbolAddress(&xhi, g_xhi); cudaGetSymbolAddress(&xlo, g_xlo);
    cudaGetSymbolAddress(&waT, g_waT); cudaGetSymbolAddress(&wpT, g_wpT);
    cudaGetSymbolAddress(&yhi, g_yhi); cudaGetSymbolAddress(&ylo, g_ylo);

    cudaFuncSetAttribute(gemm_mma<N_QKV, true>,
                         cudaFuncAttributeMaxDynamicSharedMemorySize, SMEM_GEMM);
    cudaFuncSetAttribute(gemm_mma<D_, false>,
                         cudaFuncAttributeMaxDynamicSharedMemorySize, SMEM_GEMM);
    cudaFuncSetAttribute(attn_mma,
                         cudaFuncAttributeMaxDynamicSharedMemorySize, SMEM_ATTN);

    conv_split_h<<<(M_*D_/4 + 255)/256, 256>>>(x, (fp16*)xhi, (fp16*)xlo, M_*D_/4);
    conv_wT_h<<<dim3(N_QKV/64, D_/64), 256>>>(W_attn, (fp16*)waT, N_QKV);
    conv_wT_h<<<dim3(D_/64, D_/64), 256>>>(W_proj, (fp16*)wpT, D_);

    dim3 g1(N_QKV / 128, M_ / 128);
    gemm_mma<N_QKV, true><<<g1, 256, SMEM_GEMM>>>(
        (const fp16*)xhi, (const fp16*)xlo, (const fp16*)waT, b_attn, nullptr);

    dim3 g2(S_ / 64, B_ * H_);
    attn_mma<<<g2, 128, SMEM_ATTN>>>();

    dim3 g3(D_ / 128, M_ / 128);
    gemm_mma<D_, false><<<g3, 256, SMEM_GEMM>>>(
        (const fp16*)yhi, (const fp16*)ylo, (const fp16*)wpT, b_proj, out);
}